// round 2
// baseline (speedup 1.0000x reference)
#include <cuda_runtime.h>
#include <cuda_bf16.h>

#define N_NODES 50000
#define IN_DIM  128
#define N_HEADS 8
#define OUT_DIM 16
#define HD      (N_HEADS * OUT_DIM)   // 128

// -------- scratch (static device globals; allocation-free) --------
__device__ __align__(16) float g_Q[(size_t)N_NODES * HD];
__device__ __align__(16) float g_K[(size_t)N_NODES * HD];
__device__ __align__(16) float g_V[(size_t)N_NODES * HD];
__device__ __align__(16) float g_z[(size_t)N_NODES * N_HEADS];

// =================================================================
// QKV projection: out = state @ W + b   (one of 3 selected by blockIdx.z)
// BM=64, BN=64, BK=64 (two k-chunks over IN_DIM=128), 256 threads, 4x4 tile.
// =================================================================
__global__ __launch_bounds__(256) void qkv_gemm(
    const float* __restrict__ state,
    const float* __restrict__ WQ, const float* __restrict__ bQ,
    const float* __restrict__ WK, const float* __restrict__ bK,
    const float* __restrict__ WV, const float* __restrict__ bV)
{
    const float* W;
    const float* b;
    float* out;
    if (blockIdx.z == 0)      { W = WQ; b = bQ; out = g_Q; }
    else if (blockIdx.z == 1) { W = WK; b = bK; out = g_K; }
    else                      { W = WV; b = bV; out = g_V; }

    // 68-float row stride: 272 B = 17*16 -> every As[k][4j] is 16B aligned,
    // and bank index varies with k so the transposed store phase spreads banks.
    __shared__ __align__(16) float As[64][68];   // As[k][m]
    __shared__ __align__(16) float Bs[64][64];   // Bs[k][n]

    const int row0 = blockIdx.x * 64;
    const int n0   = blockIdx.y * 64;
    const int tid  = threadIdx.x;
    const int tx   = tid & 15;     // -> n = tx*4
    const int ty   = tid >> 4;     // -> m = ty*4

    float acc[4][4];
#pragma unroll
    for (int i = 0; i < 4; i++)
#pragma unroll
        for (int j = 0; j < 4; j++) acc[i][j] = 0.0f;

    for (int k0 = 0; k0 < IN_DIM; k0 += 64) {
        // ---- load A tile (64 rows x 64 k), transposed into As[k][m] ----
#pragma unroll
        for (int i = 0; i < 4; i++) {
            int idx = tid + i * 256;         // 0..1023
            int r   = idx >> 4;              // row within tile
            int kq  = idx & 15;              // float4 index along k
            int grow = row0 + r;
            float4 a = make_float4(0.f, 0.f, 0.f, 0.f);
            if (grow < N_NODES)
                a = *reinterpret_cast<const float4*>(&state[(size_t)grow * IN_DIM + k0 + kq * 4]);
            As[kq * 4 + 0][r] = a.x;
            As[kq * 4 + 1][r] = a.y;
            As[kq * 4 + 2][r] = a.z;
            As[kq * 4 + 3][r] = a.w;
        }
        // ---- load B tile: Bs[k][n] = W[(k0+k)*HD + n0+n] ----
#pragma unroll
        for (int i = 0; i < 4; i++) {
            int idx = tid + i * 256;
            int k   = idx >> 4;
            int nq  = idx & 15;
            float4 wv = *reinterpret_cast<const float4*>(&W[(size_t)(k0 + k) * HD + n0 + nq * 4]);
            *reinterpret_cast<float4*>(&Bs[k][nq * 4]) = wv;
        }
        __syncthreads();

#pragma unroll
        for (int k = 0; k < 64; k++) {
            float4 af = *reinterpret_cast<const float4*>(&As[k][ty * 4]);
            float4 bf = *reinterpret_cast<const float4*>(&Bs[k][tx * 4]);
            float a4[4] = { af.x, af.y, af.z, af.w };
            float b4[4] = { bf.x, bf.y, bf.z, bf.w };
#pragma unroll
            for (int i = 0; i < 4; i++)
#pragma unroll
                for (int j = 0; j < 4; j++)
                    acc[i][j] = fmaf(a4[i], b4[j], acc[i][j]);
        }
        __syncthreads();
    }

    // ---- epilogue: add bias, write ----
    float4 bias = *reinterpret_cast<const float4*>(&b[n0 + tx * 4]);
#pragma unroll
    for (int i = 0; i < 4; i++) {
        int row = row0 + ty * 4 + i;
        if (row < N_NODES) {
            float4 o;
            o.x = acc[i][0] + bias.x;
            o.y = acc[i][1] + bias.y;
            o.z = acc[i][2] + bias.z;
            o.w = acc[i][3] + bias.w;
            *reinterpret_cast<float4*>(&out[(size_t)row * HD + n0 + tx * 4]) = o;
        }
    }
}

// =================================================================
// zero z
// =================================================================
__global__ void zero_z_kernel()
{
    int i = blockIdx.x * blockDim.x + threadIdx.x;
    if (i < N_NODES * N_HEADS) g_z[i] = 0.0f;
}

// =================================================================
// Edge kernel: warp per edge.
// lane l owns float4 l of the 128-float node vectors; head h = l>>2.
// =================================================================
__device__ __forceinline__ void red_add_v4(float* p, float4 v)
{
    asm volatile("red.global.add.v4.f32 [%0], {%1, %2, %3, %4};"
                 :: "l"(p), "f"(v.x), "f"(v.y), "f"(v.z), "f"(v.w)
                 : "memory");
}

__global__ __launch_bounds__(256) void edge_kernel(
    const int* __restrict__ src, const int* __restrict__ dst,
    float* __restrict__ out, int n_edges)
{
    const int warp_in_blk = threadIdx.x >> 5;
    const int lane = threadIdx.x & 31;
    const int e = blockIdx.x * (blockDim.x >> 5) + warp_in_blk;
    if (e >= n_edges) return;

    const int s = src[e];
    const int d = dst[e];

    const float4* Q4 = reinterpret_cast<const float4*>(g_Q);
    const float4* K4 = reinterpret_cast<const float4*>(g_K);
    const float4* V4 = reinterpret_cast<const float4*>(g_V);

    float4 q = Q4[(size_t)d * 32 + lane];
    float4 k = K4[(size_t)s * 32 + lane];

    float part = q.x * k.x + q.y * k.y + q.z * k.z + q.w * k.w;
    part += __shfl_xor_sync(0xFFFFFFFFu, part, 1);
    part += __shfl_xor_sync(0xFFFFFFFFu, part, 2);
    // part now = full head dot for head (lane>>2), replicated over the 4 lanes

    float sc = part * 0.25f;                       // / sqrt(OUT_DIM=16)
    sc = fminf(fmaxf(sc, -5.0f), 5.0f);
    float w = __expf(sc);

    float4 v = V4[(size_t)s * 32 + lane];
    float4 wv = make_float4(v.x * w, v.y * w, v.z * w, v.w * w);

    red_add_v4(&out[(size_t)d * HD + lane * 4], wv);

    if ((lane & 3) == 0) {
        atomicAdd(&g_z[(size_t)d * N_HEADS + (lane >> 2)], w);
    }
}

// =================================================================
// Normalize in place: out[n,h,d] /= z[n,h]
// =================================================================
__global__ void normalize_kernel(float* __restrict__ out)
{
    int i = blockIdx.x * blockDim.x + threadIdx.x;   // float4 index
    if (i < N_NODES * 32) {
        float4 v = reinterpret_cast<float4*>(out)[i];
        float inv = 1.0f / g_z[i >> 2];
        v.x *= inv; v.y *= inv; v.z *= inv; v.w *= inv;
        reinterpret_cast<float4*>(out)[i] = v;
    }
}

// =================================================================
extern "C" void kernel_launch(void* const* d_in, const int* in_sizes, int n_in,
                              void* d_out, int out_size)
{
    const float* state = (const float*)d_in[0];
    const int*   src   = (const int*)d_in[1];
    const int*   dst   = (const int*)d_in[2];
    const float* WQ    = (const float*)d_in[3];
    const float* bQ    = (const float*)d_in[4];
    const float* WK    = (const float*)d_in[5];
    const float* bK    = (const float*)d_in[6];
    const float* WV    = (const float*)d_in[7];
    const float* bV    = (const float*)d_in[8];
    float* out = (float*)d_out;

    const int n_edges = in_sizes[1];

    // zero accumulators
    cudaMemsetAsync(d_out, 0, (size_t)N_NODES * HD * sizeof(float), 0);
    zero_z_kernel<<<(N_NODES * N_HEADS + 255) / 256, 256>>>();

    // QKV projections
    dim3 ggrid((N_NODES + 63) / 64, HD / 64, 3);
    qkv_gemm<<<ggrid, 256>>>(state, WQ, bQ, WK, bK, WV, bV);

    // edge phase (warp per edge; 8 edges per 256-thread block)
    int eblocks = (n_edges + 7) / 8;
    edge_kernel<<<eblocks, 256>>>(src, dst, out, n_edges);

    // normalize
    normalize_kernel<<<(N_NODES * 32 + 255) / 256, 256>>>(out);
}

// round 3
// speedup vs baseline: 1.1838x; 1.1838x over previous
#include <cuda_runtime.h>
#include <cuda_fp16.h>

#define N_NODES 50000
#define IN_DIM  128
#define N_HEADS 8
#define OUT_DIM 16
#define HD      (N_HEADS * OUT_DIM)   // 128

// -------- scratch (static device globals; allocation-free) --------
__device__ __align__(16) __half g_Qh[(size_t)N_NODES * HD];
__device__ __align__(16) __half g_Kh[(size_t)N_NODES * HD];
__device__ __align__(16) float  g_V [(size_t)N_NODES * HD];
__device__ __align__(16) float  g_z [(size_t)N_NODES * N_HEADS];

// =================================================================
// QKV projection: out = state @ W + b, one of Q/K/V per blockIdx.z.
// BM=128, BN=128(=HD), BK=32, 256 threads, 8x8 per-thread tile.
// Q,K written as fp16; V as fp32.
// =================================================================
__global__ __launch_bounds__(256) void qkv_gemm(
    const float* __restrict__ state,
    const float* __restrict__ WQ, const float* __restrict__ bQ,
    const float* __restrict__ WK, const float* __restrict__ bK,
    const float* __restrict__ WV, const float* __restrict__ bV)
{
    const float* W;
    const float* b;
    if (blockIdx.z == 0)      { W = WQ; b = bQ; }
    else if (blockIdx.z == 1) { W = WK; b = bK; }
    else                      { W = WV; b = bV; }

    // As stride 132 floats = 528B (16B aligned per row start of any 4-group)
    __shared__ __align__(16) float As[32][132];   // As[k][m]
    __shared__ __align__(16) float Bs[32][128];   // Bs[k][n]

    const int row0 = blockIdx.x * 128;
    const int tid  = threadIdx.x;
    const int tx   = tid & 15;     // n = tx*8
    const int ty   = tid >> 4;     // m = ty*8

    float acc[8][8];
#pragma unroll
    for (int i = 0; i < 8; i++)
#pragma unroll
        for (int j = 0; j < 8; j++) acc[i][j] = 0.0f;

    for (int k0 = 0; k0 < IN_DIM; k0 += 32) {
        // ---- A tile: 128 rows x 32 k, transposed into As[k][m] ----
#pragma unroll
        for (int i = 0; i < 4; i++) {
            int idx = tid + i * 256;       // 0..1023
            int r   = idx >> 3;            // row in tile (0..127)
            int kq  = idx & 7;             // float4 index along k
            int grow = row0 + r;
            float4 a = make_float4(0.f, 0.f, 0.f, 0.f);
            if (grow < N_NODES)
                a = *reinterpret_cast<const float4*>(&state[(size_t)grow * IN_DIM + k0 + kq * 4]);
            As[kq * 4 + 0][r] = a.x;
            As[kq * 4 + 1][r] = a.y;
            As[kq * 4 + 2][r] = a.z;
            As[kq * 4 + 3][r] = a.w;
        }
        // ---- B tile: Bs[k][n] = W[(k0+k)*HD + n] ----
#pragma unroll
        for (int i = 0; i < 4; i++) {
            int idx = tid + i * 256;
            int k   = idx >> 5;            // 0..31
            int nq  = idx & 31;            // float4 along n
            float4 wv = *reinterpret_cast<const float4*>(&W[(size_t)(k0 + k) * HD + nq * 4]);
            *reinterpret_cast<float4*>(&Bs[k][nq * 4]) = wv;
        }
        __syncthreads();

#pragma unroll
        for (int k = 0; k < 32; k++) {
            float4 a0 = *reinterpret_cast<const float4*>(&As[k][ty * 8]);
            float4 a1 = *reinterpret_cast<const float4*>(&As[k][ty * 8 + 4]);
            float4 b0 = *reinterpret_cast<const float4*>(&Bs[k][tx * 8]);
            float4 b1 = *reinterpret_cast<const float4*>(&Bs[k][tx * 8 + 4]);
            float av[8] = { a0.x, a0.y, a0.z, a0.w, a1.x, a1.y, a1.z, a1.w };
            float bv[8] = { b0.x, b0.y, b0.z, b0.w, b1.x, b1.y, b1.z, b1.w };
#pragma unroll
            for (int i = 0; i < 8; i++)
#pragma unroll
                for (int j = 0; j < 8; j++)
                    acc[i][j] = fmaf(av[i], bv[j], acc[i][j]);
        }
        __syncthreads();
    }

    // ---- epilogue ----
    float bias[8];
#pragma unroll
    for (int j = 0; j < 8; j++) bias[j] = b[tx * 8 + j];

#pragma unroll
    for (int i = 0; i < 8; i++) {
        int row = row0 + ty * 8 + i;
        if (row >= N_NODES) continue;
        float o[8];
#pragma unroll
        for (int j = 0; j < 8; j++) o[j] = acc[i][j] + bias[j];

        if (blockIdx.z < 2) {
            __half* outh = (blockIdx.z == 0) ? g_Qh : g_Kh;
            __half2 h[4];
#pragma unroll
            for (int j = 0; j < 4; j++)
                h[j] = __floats2half2_rn(o[2 * j], o[2 * j + 1]);
            *reinterpret_cast<uint4*>(&outh[(size_t)row * HD + tx * 8]) =
                *reinterpret_cast<const uint4*>(h);
        } else {
            float4 f0 = make_float4(o[0], o[1], o[2], o[3]);
            float4 f1 = make_float4(o[4], o[5], o[6], o[7]);
            *reinterpret_cast<float4*>(&g_V[(size_t)row * HD + tx * 8])     = f0;
            *reinterpret_cast<float4*>(&g_V[(size_t)row * HD + tx * 8 + 4]) = f1;
        }
    }
}

// =================================================================
__global__ void zero_z_kernel()
{
    int i = blockIdx.x * blockDim.x + threadIdx.x;
    if (i < N_NODES * N_HEADS) g_z[i] = 0.0f;
}

// =================================================================
// Edge kernel: warp per edge. lane l owns dims [4l, 4l+4) of the
// 128-dim node vectors; head h = l>>2 (16 dims = 4 lanes).
// Q/K gathered in fp16 (8B per lane), V in fp32 (16B per lane).
// =================================================================
__device__ __forceinline__ void red_add_v4(float* p, float4 v)
{
    asm volatile("red.global.add.v4.f32 [%0], {%1, %2, %3, %4};"
                 :: "l"(p), "f"(v.x), "f"(v.y), "f"(v.z), "f"(v.w)
                 : "memory");
}

__global__ __launch_bounds__(256) void edge_kernel(
    const int* __restrict__ src, const int* __restrict__ dst,
    float* __restrict__ out, int n_edges)
{
    const int warp_in_blk = threadIdx.x >> 5;
    const int lane = threadIdx.x & 31;
    const int e = blockIdx.x * 8 + warp_in_blk;
    if (e >= n_edges) return;

    const int s = src[e];
    const int d = dst[e];

    const uint2* Qh2 = reinterpret_cast<const uint2*>(g_Qh);  // 4 halves each
    const uint2* Kh2 = reinterpret_cast<const uint2*>(g_Kh);
    const float4* V4 = reinterpret_cast<const float4*>(g_V);

    uint2 qr = Qh2[(size_t)d * 32 + lane];
    uint2 kr = Kh2[(size_t)s * 32 + lane];

    float2 q01 = __half22float2(*reinterpret_cast<const __half2*>(&qr.x));
    float2 q23 = __half22float2(*reinterpret_cast<const __half2*>(&qr.y));
    float2 k01 = __half22float2(*reinterpret_cast<const __half2*>(&kr.x));
    float2 k23 = __half22float2(*reinterpret_cast<const __half2*>(&kr.y));

    float part = q01.x * k01.x + q01.y * k01.y + q23.x * k23.x + q23.y * k23.y;
    part += __shfl_xor_sync(0xFFFFFFFFu, part, 1);
    part += __shfl_xor_sync(0xFFFFFFFFu, part, 2);
    // part = head dot for head (lane>>2), replicated across its 4 lanes

    float sc = part * 0.25f;                       // / sqrt(OUT_DIM=16)
    sc = fminf(fmaxf(sc, -5.0f), 5.0f);
    float w = __expf(sc);

    float4 v = V4[(size_t)s * 32 + lane];
    float4 wv = make_float4(v.x * w, v.y * w, v.z * w, v.w * w);

    red_add_v4(&out[(size_t)d * HD + lane * 4], wv);

    // z: gather head weights to lanes 0 and 16, two vector REDs.
    int base = lane & 16;
    float z0 = __shfl_sync(0xFFFFFFFFu, w, base + 0);
    float z1 = __shfl_sync(0xFFFFFFFFu, w, base + 4);
    float z2 = __shfl_sync(0xFFFFFFFFu, w, base + 8);
    float z3 = __shfl_sync(0xFFFFFFFFu, w, base + 12);
    if ((lane & 15) == 0)
        red_add_v4(&g_z[(size_t)d * N_HEADS + (lane >> 4) * 4],
                   make_float4(z0, z1, z2, z3));
}

// =================================================================
__global__ void normalize_kernel(float* __restrict__ out)
{
    int i = blockIdx.x * blockDim.x + threadIdx.x;   // float4 index
    if (i < N_NODES * 32) {
        float4 v = reinterpret_cast<float4*>(out)[i];
        float inv = 1.0f / g_z[i >> 2];
        v.x *= inv; v.y *= inv; v.z *= inv; v.w *= inv;
        reinterpret_cast<float4*>(out)[i] = v;
    }
}

// =================================================================
extern "C" void kernel_launch(void* const* d_in, const int* in_sizes, int n_in,
                              void* d_out, int out_size)
{
    const float* state = (const float*)d_in[0];
    const int*   src   = (const int*)d_in[1];
    const int*   dst   = (const int*)d_in[2];
    const float* WQ    = (const float*)d_in[3];
    const float* bQ    = (const float*)d_in[4];
    const float* WK    = (const float*)d_in[5];
    const float* bK    = (const float*)d_in[6];
    const float* WV    = (const float*)d_in[7];
    const float* bV    = (const float*)d_in[8];
    float* out = (float*)d_out;

    const int n_edges = in_sizes[1];

    // zero accumulators
    cudaMemsetAsync(d_out, 0, (size_t)N_NODES * HD * sizeof(float), 0);
    zero_z_kernel<<<(N_NODES * N_HEADS + 255) / 256, 256>>>();

    // QKV projections (z: 0=Q fp16, 1=K fp16, 2=V fp32)
    dim3 ggrid((N_NODES + 127) / 128, 1, 3);
    qkv_gemm<<<ggrid, 256>>>(state, WQ, bQ, WK, bK, WV, bV);

    // edge phase (warp per edge; 8 edges per 256-thread block)
    int eblocks = (n_edges + 7) / 8;
    edge_kernel<<<eblocks, 256>>>(src, dst, out, n_edges);

    // normalize
    normalize_kernel<<<(N_NODES * 32 + 255) / 256, 256>>>(out);
}

// round 4
// speedup vs baseline: 1.2572x; 1.0620x over previous
#include <cuda_runtime.h>
#include <cuda_fp16.h>

#define N_NODES 50000
#define IN_DIM  128
#define N_HEADS 8
#define OUT_DIM 16
#define HD      (N_HEADS * OUT_DIM)   // 128

// -------- scratch (static device globals; allocation-free) --------
__device__ __align__(16) __half g_Qh[(size_t)N_NODES * HD];
__device__ __align__(16) __half g_Kh[(size_t)N_NODES * HD];
__device__ __align__(16) __half g_Vh[(size_t)N_NODES * HD];
__device__ __align__(16) float  g_z [(size_t)N_NODES * N_HEADS];

// ---- packed f32x2 helpers (Blackwell: 2x fp32 FMA per instruction) ----
#define PACK2(p, lo, hi) \
    asm("mov.b64 %0, {%1, %2};" : "=l"(p) : "f"(lo), "f"(hi))
#define UNPACK2(lo, hi, p) \
    asm("mov.b64 {%0, %1}, %2;" : "=f"(lo), "=f"(hi) : "l"(p))
#define FMA2(d, a, b) \
    asm("fma.rn.f32x2 %0, %1, %2, %0;" : "+l"(d) : "l"(a), "l"(b))

// =================================================================
// QKV projection: out = state @ W + b, one of Q/K/V per blockIdx.z.
// BM=128, BN=128(=HD), BK=32, 256 threads, 8x8 per-thread tile,
// inner loop in packed f32x2 FMAs (2x fp32 rate). All outputs fp16.
// =================================================================
__global__ __launch_bounds__(256) void qkv_gemm(
    const float* __restrict__ state,
    const float* __restrict__ WQ, const float* __restrict__ bQ,
    const float* __restrict__ WK, const float* __restrict__ bK,
    const float* __restrict__ WV, const float* __restrict__ bV)
{
    const float* W;
    const float* b;
    __half* outh;
    if (blockIdx.z == 0)      { W = WQ; b = bQ; outh = g_Qh; }
    else if (blockIdx.z == 1) { W = WK; b = bK; outh = g_Kh; }
    else                      { W = WV; b = bV; outh = g_Vh; }

    __shared__ __align__(16) float As[32][132];   // As[k][m], 528B row stride
    __shared__ __align__(16) float Bs[32][128];   // Bs[k][n]

    const int row0 = blockIdx.x * 128;
    const int tid  = threadIdx.x;
    const int tx   = tid & 15;     // n = tx*8
    const int ty   = tid >> 4;     // m = ty*8

    unsigned long long acc[8][4];  // [i][jpair], each = 2 packed fp32
#pragma unroll
    for (int i = 0; i < 8; i++)
#pragma unroll
        for (int p = 0; p < 4; p++) acc[i][p] = 0ULL;

    for (int k0 = 0; k0 < IN_DIM; k0 += 32) {
        // ---- A tile: 128 rows x 32 k, transposed into As[k][m] ----
#pragma unroll
        for (int i = 0; i < 4; i++) {
            int idx = tid + i * 256;       // 0..1023
            int r   = idx >> 3;            // row in tile (0..127)
            int kq  = idx & 7;             // float4 index along k
            int grow = row0 + r;
            float4 a = make_float4(0.f, 0.f, 0.f, 0.f);
            if (grow < N_NODES)
                a = *reinterpret_cast<const float4*>(&state[(size_t)grow * IN_DIM + k0 + kq * 4]);
            As[kq * 4 + 0][r] = a.x;
            As[kq * 4 + 1][r] = a.y;
            As[kq * 4 + 2][r] = a.z;
            As[kq * 4 + 3][r] = a.w;
        }
        // ---- B tile: Bs[k][n] = W[(k0+k)*HD + n] ----
#pragma unroll
        for (int i = 0; i < 4; i++) {
            int idx = tid + i * 256;
            int k   = idx >> 5;            // 0..31
            int nq  = idx & 31;            // float4 along n
            float4 wv = *reinterpret_cast<const float4*>(&W[(size_t)(k0 + k) * HD + nq * 4]);
            *reinterpret_cast<float4*>(&Bs[k][nq * 4]) = wv;
        }
        __syncthreads();

#pragma unroll
        for (int k = 0; k < 32; k++) {
            float4 a0 = *reinterpret_cast<const float4*>(&As[k][ty * 8]);
            float4 a1 = *reinterpret_cast<const float4*>(&As[k][ty * 8 + 4]);
            float4 b0 = *reinterpret_cast<const float4*>(&Bs[k][tx * 8]);
            float4 b1 = *reinterpret_cast<const float4*>(&Bs[k][tx * 8 + 4]);

            unsigned long long bp[4];
            PACK2(bp[0], b0.x, b0.y);
            PACK2(bp[1], b0.z, b0.w);
            PACK2(bp[2], b1.x, b1.y);
            PACK2(bp[3], b1.z, b1.w);

            float av[8] = { a0.x, a0.y, a0.z, a0.w, a1.x, a1.y, a1.z, a1.w };
#pragma unroll
            for (int i = 0; i < 8; i++) {
                unsigned long long ap;
                PACK2(ap, av[i], av[i]);
#pragma unroll
                for (int p = 0; p < 4; p++)
                    FMA2(acc[i][p], ap, bp[p]);
            }
        }
        __syncthreads();
    }

    // ---- epilogue: unpack, add bias, convert fp16, store 16B ----
    float bias[8];
#pragma unroll
    for (int j = 0; j < 8; j++) bias[j] = b[tx * 8 + j];

#pragma unroll
    for (int i = 0; i < 8; i++) {
        int row = row0 + ty * 8 + i;
        if (row >= N_NODES) continue;
        float o[8];
#pragma unroll
        for (int p = 0; p < 4; p++) {
            float lo, hi;
            UNPACK2(lo, hi, acc[i][p]);
            o[2 * p]     = lo + bias[2 * p];
            o[2 * p + 1] = hi + bias[2 * p + 1];
        }
        __half2 h[4];
#pragma unroll
        for (int j = 0; j < 4; j++)
            h[j] = __floats2half2_rn(o[2 * j], o[2 * j + 1]);
        *reinterpret_cast<uint4*>(&outh[(size_t)row * HD + tx * 8]) =
            *reinterpret_cast<const uint4*>(h);
    }
}

// =================================================================
__global__ void zero_z_kernel()
{
    int i = blockIdx.x * blockDim.x + threadIdx.x;
    if (i < N_NODES * N_HEADS) g_z[i] = 0.0f;
}

// =================================================================
// Edge kernel: warp per edge. lane l owns dims [4l, 4l+4);
// head h = l>>2. Q/K/V all fp16 gathers (8B per lane each);
// accumulation into out/z stays fp32 via red.global.add.v4.
// =================================================================
__device__ __forceinline__ void red_add_v4(float* p, float4 v)
{
    asm volatile("red.global.add.v4.f32 [%0], {%1, %2, %3, %4};"
                 :: "l"(p), "f"(v.x), "f"(v.y), "f"(v.z), "f"(v.w)
                 : "memory");
}

__global__ __launch_bounds__(256) void edge_kernel(
    const int* __restrict__ src, const int* __restrict__ dst,
    float* __restrict__ out, int n_edges)
{
    const int warp_in_blk = threadIdx.x >> 5;
    const int lane = threadIdx.x & 31;
    const int e = blockIdx.x * 8 + warp_in_blk;
    if (e >= n_edges) return;

    const int s = src[e];
    const int d = dst[e];

    const uint2* Qh2 = reinterpret_cast<const uint2*>(g_Qh);  // 4 halves
    const uint2* Kh2 = reinterpret_cast<const uint2*>(g_Kh);
    const uint2* Vh2 = reinterpret_cast<const uint2*>(g_Vh);

    uint2 qr = Qh2[(size_t)d * 32 + lane];
    uint2 kr = Kh2[(size_t)s * 32 + lane];

    float2 q01 = __half22float2(*reinterpret_cast<const __half2*>(&qr.x));
    float2 q23 = __half22float2(*reinterpret_cast<const __half2*>(&qr.y));
    float2 k01 = __half22float2(*reinterpret_cast<const __half2*>(&kr.x));
    float2 k23 = __half22float2(*reinterpret_cast<const __half2*>(&kr.y));

    float part = q01.x * k01.x + q01.y * k01.y + q23.x * k23.x + q23.y * k23.y;
    part += __shfl_xor_sync(0xFFFFFFFFu, part, 1);
    part += __shfl_xor_sync(0xFFFFFFFFu, part, 2);
    // part = head dot for head (lane>>2), replicated across its 4 lanes

    float sc = part * 0.25f;                       // / sqrt(OUT_DIM=16)
    sc = fminf(fmaxf(sc, -5.0f), 5.0f);
    float w = __expf(sc);

    uint2 vr = Vh2[(size_t)s * 32 + lane];
    float2 v01 = __half22float2(*reinterpret_cast<const __half2*>(&vr.x));
    float2 v23 = __half22float2(*reinterpret_cast<const __half2*>(&vr.y));
    float4 wv = make_float4(v01.x * w, v01.y * w, v23.x * w, v23.y * w);

    red_add_v4(&out[(size_t)d * HD + lane * 4], wv);

    // z: gather head weights to lanes 0 and 16, two vector REDs.
    int base = lane & 16;
    float z0 = __shfl_sync(0xFFFFFFFFu, w, base + 0);
    float z1 = __shfl_sync(0xFFFFFFFFu, w, base + 4);
    float z2 = __shfl_sync(0xFFFFFFFFu, w, base + 8);
    float z3 = __shfl_sync(0xFFFFFFFFu, w, base + 12);
    if ((lane & 15) == 0)
        red_add_v4(&g_z[(size_t)d * N_HEADS + (lane >> 4) * 4],
                   make_float4(z0, z1, z2, z3));
}

// =================================================================
__global__ void normalize_kernel(float* __restrict__ out)
{
    int i = blockIdx.x * blockDim.x + threadIdx.x;   // float4 index
    if (i < N_NODES * 32) {
        float4 v = reinterpret_cast<float4*>(out)[i];
        float inv = 1.0f / g_z[i >> 2];
        v.x *= inv; v.y *= inv; v.z *= inv; v.w *= inv;
        reinterpret_cast<float4*>(out)[i] = v;
    }
}

// =================================================================
extern "C" void kernel_launch(void* const* d_in, const int* in_sizes, int n_in,
                              void* d_out, int out_size)
{
    const float* state = (const float*)d_in[0];
    const int*   src   = (const int*)d_in[1];
    const int*   dst   = (const int*)d_in[2];
    const float* WQ    = (const float*)d_in[3];
    const float* bQ    = (const float*)d_in[4];
    const float* WK    = (const float*)d_in[5];
    const float* bK    = (const float*)d_in[6];
    const float* WV    = (const float*)d_in[7];
    const float* bV    = (const float*)d_in[8];
    float* out = (float*)d_out;

    const int n_edges = in_sizes[1];

    // zero accumulators
    cudaMemsetAsync(d_out, 0, (size_t)N_NODES * HD * sizeof(float), 0);
    zero_z_kernel<<<(N_NODES * N_HEADS + 255) / 256, 256>>>();

    // QKV projections (z: 0=Q, 1=K, 2=V; all fp16 outputs)
    dim3 ggrid((N_NODES + 127) / 128, 1, 3);
    qkv_gemm<<<ggrid, 256>>>(state, WQ, bQ, WK, bK, WV, bV);

    // edge phase (warp per edge; 8 edges per 256-thread block)
    int eblocks = (n_edges + 7) / 8;
    edge_kernel<<<eblocks, 256>>>(src, dst, out, n_edges);

    // normalize
    normalize_kernel<<<(N_NODES * 32 + 255) / 256, 256>>>(out);
}

// round 5
// speedup vs baseline: 1.3367x; 1.0633x over previous
#include <cuda_runtime.h>
#include <cuda_fp16.h>

#define N_NODES  50000
#define IN_DIM   128
#define N_HEADS  8
#define OUT_DIM  16
#define HD       (N_HEADS * OUT_DIM)   // 128
#define MAX_EDGES 1600000

// -------- scratch (static device globals; allocation-free) --------
__device__ __align__(16) __half g_Qh[(size_t)N_NODES * HD];
__device__ __align__(16) __half g_Kh[(size_t)N_NODES * HD];
__device__ __align__(16) __half g_Vh[(size_t)N_NODES * HD];
__device__ int g_hist[N_NODES];
__device__ int g_rowptr[N_NODES + 1];
__device__ int g_cursor[N_NODES];
__device__ int g_srcsorted[MAX_EDGES];

// ---- packed f32x2 helpers (Blackwell: 2x fp32 FMA per instruction) ----
#define PACK2(p, lo, hi) \
    asm("mov.b64 %0, {%1, %2};" : "=l"(p) : "f"(lo), "f"(hi))
#define UNPACK2(lo, hi, p) \
    asm("mov.b64 {%0, %1}, %2;" : "=f"(lo), "=f"(hi) : "l"(p))
#define FMA2(d, a, b) \
    asm("fma.rn.f32x2 %0, %1, %2, %0;" : "+l"(d) : "l"(a), "l"(b))

// =================================================================
// CSR build: histogram -> scan -> scatter (counting sort by dst)
// =================================================================
__global__ void zero_hist_kernel()
{
    int i = blockIdx.x * blockDim.x + threadIdx.x;
    if (i < N_NODES) g_hist[i] = 0;
}

__global__ void hist_kernel(const int* __restrict__ dst, int n_edges)
{
    int e = blockIdx.x * blockDim.x + threadIdx.x;
    if (e < n_edges) atomicAdd(&g_hist[dst[e]], 1);
}

// single block, 1024 threads; 50000 entries, 49 per thread
__global__ __launch_bounds__(1024) void scan_kernel()
{
    __shared__ int part[1024];
    const int CHUNK = 49;
    int t = threadIdx.x;
    int begin = t * CHUNK;
    int end   = begin + CHUNK; if (end > N_NODES) end = N_NODES;
    if (begin > N_NODES) begin = N_NODES;

    int s = 0;
    for (int i = begin; i < end; i++) s += g_hist[i];
    part[t] = s;
    __syncthreads();

    // Hillis-Steele inclusive scan
    for (int off = 1; off < 1024; off <<= 1) {
        int v = (t >= off) ? part[t - off] : 0;
        __syncthreads();
        part[t] += v;
        __syncthreads();
    }

    int base = (t == 0) ? 0 : part[t - 1];
    for (int i = begin; i < end; i++) {
        g_rowptr[i] = base;
        g_cursor[i] = base;
        base += g_hist[i];
    }
    if (t == 1023) g_rowptr[N_NODES] = part[1023];
}

__global__ void scatter_kernel(const int* __restrict__ src,
                               const int* __restrict__ dst, int n_edges)
{
    int e = blockIdx.x * blockDim.x + threadIdx.x;
    if (e < n_edges) {
        int d = dst[e];
        int pos = atomicAdd(&g_cursor[d], 1);
        g_srcsorted[pos] = src[e];
    }
}

// =================================================================
// QKV projection: out = state @ W + b, one of Q/K/V per blockIdx.z.
// BM=128, BN=128(=HD), BK=32, 256 threads, 8x8 per-thread tile,
// packed f32x2 FMAs. All outputs fp16.
// =================================================================
__global__ __launch_bounds__(256) void qkv_gemm(
    const float* __restrict__ state,
    const float* __restrict__ WQ, const float* __restrict__ bQ,
    const float* __restrict__ WK, const float* __restrict__ bK,
    const float* __restrict__ WV, const float* __restrict__ bV)
{
    const float* W;
    const float* b;
    __half* outh;
    if (blockIdx.z == 0)      { W = WQ; b = bQ; outh = g_Qh; }
    else if (blockIdx.z == 1) { W = WK; b = bK; outh = g_Kh; }
    else                      { W = WV; b = bV; outh = g_Vh; }

    __shared__ __align__(16) float As[32][132];   // As[k][m], 528B row stride
    __shared__ __align__(16) float Bs[32][128];   // Bs[k][n]

    const int row0 = blockIdx.x * 128;
    const int tid  = threadIdx.x;
    const int tx   = tid & 15;     // n = tx*8
    const int ty   = tid >> 4;     // m = ty*8

    unsigned long long acc[8][4];
#pragma unroll
    for (int i = 0; i < 8; i++)
#pragma unroll
        for (int p = 0; p < 4; p++) acc[i][p] = 0ULL;

    for (int k0 = 0; k0 < IN_DIM; k0 += 32) {
#pragma unroll
        for (int i = 0; i < 4; i++) {
            int idx = tid + i * 256;       // 0..1023
            int r   = idx >> 3;            // row in tile (0..127)
            int kq  = idx & 7;             // float4 index along k
            int grow = row0 + r;
            float4 a = make_float4(0.f, 0.f, 0.f, 0.f);
            if (grow < N_NODES)
                a = *reinterpret_cast<const float4*>(&state[(size_t)grow * IN_DIM + k0 + kq * 4]);
            As[kq * 4 + 0][r] = a.x;
            As[kq * 4 + 1][r] = a.y;
            As[kq * 4 + 2][r] = a.z;
            As[kq * 4 + 3][r] = a.w;
        }
#pragma unroll
        for (int i = 0; i < 4; i++) {
            int idx = tid + i * 256;
            int k   = idx >> 5;            // 0..31
            int nq  = idx & 31;            // float4 along n
            float4 wv = *reinterpret_cast<const float4*>(&W[(size_t)(k0 + k) * HD + nq * 4]);
            *reinterpret_cast<float4*>(&Bs[k][nq * 4]) = wv;
        }
        __syncthreads();

#pragma unroll
        for (int k = 0; k < 32; k++) {
            float4 a0 = *reinterpret_cast<const float4*>(&As[k][ty * 8]);
            float4 a1 = *reinterpret_cast<const float4*>(&As[k][ty * 8 + 4]);
            float4 b0 = *reinterpret_cast<const float4*>(&Bs[k][tx * 8]);
            float4 b1 = *reinterpret_cast<const float4*>(&Bs[k][tx * 8 + 4]);

            unsigned long long bp[4];
            PACK2(bp[0], b0.x, b0.y);
            PACK2(bp[1], b0.z, b0.w);
            PACK2(bp[2], b1.x, b1.y);
            PACK2(bp[3], b1.z, b1.w);

            float av[8] = { a0.x, a0.y, a0.z, a0.w, a1.x, a1.y, a1.z, a1.w };
#pragma unroll
            for (int i = 0; i < 8; i++) {
                unsigned long long ap;
                PACK2(ap, av[i], av[i]);
#pragma unroll
                for (int p = 0; p < 4; p++)
                    FMA2(acc[i][p], ap, bp[p]);
            }
        }
        __syncthreads();
    }

    float bias[8];
#pragma unroll
    for (int j = 0; j < 8; j++) bias[j] = b[tx * 8 + j];

#pragma unroll
    for (int i = 0; i < 8; i++) {
        int row = row0 + ty * 8 + i;
        if (row >= N_NODES) continue;
        float o[8];
#pragma unroll
        for (int p = 0; p < 4; p++) {
            float lo, hi;
            UNPACK2(lo, hi, acc[i][p]);
            o[2 * p]     = lo + bias[2 * p];
            o[2 * p + 1] = hi + bias[2 * p + 1];
        }
        __half2 h[4];
#pragma unroll
        for (int j = 0; j < 4; j++)
            h[j] = __floats2half2_rn(o[2 * j], o[2 * j + 1]);
        *reinterpret_cast<uint4*>(&outh[(size_t)row * HD + tx * 8]) =
            *reinterpret_cast<const uint4*>(h);
    }
}

// =================================================================
// Aggregate: warp per dst node. lane l owns dims [4l,4l+4);
// head h = l>>2. Q resident in registers; per edge only K,V fp16
// gathers. Register accumulation, fused normalize, single store.
// Software-pipelined depth 2.
// =================================================================
__global__ __launch_bounds__(256) void aggregate_kernel(float* __restrict__ out)
{
    const int warp = threadIdx.x >> 5;
    const int lane = threadIdx.x & 31;
    const int n = blockIdx.x * 8 + warp;
    if (n >= N_NODES) return;

    const uint2* Qh2 = reinterpret_cast<const uint2*>(g_Qh);
    const uint2* Kh2 = reinterpret_cast<const uint2*>(g_Kh);
    const uint2* Vh2 = reinterpret_cast<const uint2*>(g_Vh);

    uint2 qr = Qh2[(size_t)n * 32 + lane];
    float2 q01 = __half22float2(*reinterpret_cast<const __half2*>(&qr.x));
    float2 q23 = __half22float2(*reinterpret_cast<const __half2*>(&qr.y));

    int i   = g_rowptr[n];
    const int end = g_rowptr[n + 1];

    float a0 = 0.f, a1 = 0.f, a2 = 0.f, a3 = 0.f, z = 0.f;

    uint2 kr = make_uint2(0u, 0u), vr = make_uint2(0u, 0u);
    if (i < end) {
        int s = g_srcsorted[i];
        kr = Kh2[(size_t)s * 32 + lane];
        vr = Vh2[(size_t)s * 32 + lane];
    }

    while (i < end) {
        // prefetch next edge
        uint2 krn = kr, vrn = vr;
        int inext = i + 1;
        if (inext < end) {
            int s2 = g_srcsorted[inext];
            krn = Kh2[(size_t)s2 * 32 + lane];
            vrn = Vh2[(size_t)s2 * 32 + lane];
        }

        float2 k01 = __half22float2(*reinterpret_cast<const __half2*>(&kr.x));
        float2 k23 = __half22float2(*reinterpret_cast<const __half2*>(&kr.y));

        float part = q01.x * k01.x + q01.y * k01.y + q23.x * k23.x + q23.y * k23.y;
        part += __shfl_xor_sync(0xFFFFFFFFu, part, 1);
        part += __shfl_xor_sync(0xFFFFFFFFu, part, 2);
        // head dot for head (lane>>2), replicated across its 4 lanes

        float sc = part * 0.25f;
        sc = fminf(fmaxf(sc, -5.0f), 5.0f);
        float w = __expf(sc);

        float2 v01 = __half22float2(*reinterpret_cast<const __half2*>(&vr.x));
        float2 v23 = __half22float2(*reinterpret_cast<const __half2*>(&vr.y));

        a0 = fmaf(w, v01.x, a0);
        a1 = fmaf(w, v01.y, a1);
        a2 = fmaf(w, v23.x, a2);
        a3 = fmaf(w, v23.y, a3);
        z += w;

        kr = krn; vr = vrn; i = inext;
    }

    float inv = 1.0f / z;
    float4 o = make_float4(a0 * inv, a1 * inv, a2 * inv, a3 * inv);
    *reinterpret_cast<float4*>(&out[(size_t)n * HD + lane * 4]) = o;
}

// =================================================================
extern "C" void kernel_launch(void* const* d_in, const int* in_sizes, int n_in,
                              void* d_out, int out_size)
{
    const float* state = (const float*)d_in[0];
    const int*   src   = (const int*)d_in[1];
    const int*   dst   = (const int*)d_in[2];
    const float* WQ    = (const float*)d_in[3];
    const float* bQ    = (const float*)d_in[4];
    const float* WK    = (const float*)d_in[5];
    const float* bK    = (const float*)d_in[6];
    const float* WV    = (const float*)d_in[7];
    const float* bV    = (const float*)d_in[8];
    float* out = (float*)d_out;

    const int n_edges = in_sizes[1];

    // ---- CSR build (counting sort by dst) ----
    zero_hist_kernel<<<(N_NODES + 255) / 256, 256>>>();
    hist_kernel<<<(n_edges + 255) / 256, 256>>>(dst, n_edges);
    scan_kernel<<<1, 1024>>>();
    scatter_kernel<<<(n_edges + 255) / 256, 256>>>(src, dst, n_edges);

    // ---- QKV projections (z: 0=Q, 1=K, 2=V; fp16 outputs) ----
    dim3 ggrid((N_NODES + 127) / 128, 1, 3);
    qkv_gemm<<<ggrid, 256>>>(state, WQ, bQ, WK, bK, WV, bV);

    // ---- fused gather + attention + aggregate + normalize ----
    aggregate_kernel<<<(N_NODES + 7) / 8, 256>>>(out);
}